// round 3
// baseline (speedup 1.0000x reference)
#include <cuda_runtime.h>
#include <cuda_bf16.h>
#include <stdint.h>

// ============================================================================
// StressNN on GB300 (sm_103a, built at plain sm_103 PTX target -> HMMA path)
//   features (FFt, det, analytic 3x3 SVD sigma) + 7-layer MLP, exact GELU
//   GEMMs: mma.sync m16n8k16 bf16, 3-way split (hi@Whi + hi@Wlo + lo@Whi)
// ============================================================================

#define TILE_M   256
#define THREADS  512

// ---- dynamic shared memory layout (bytes) ----
#define OFF_XHI   0          // [2 chunks][256 rows][128B] swizzled
#define OFF_XLO   65536
#define OFF_WHI   131072     // [2 chunks][128 rows][128B] swizzled
#define OFF_WLO   163840
#define OFF_BIAS  196608     // 7*128 floats
#define OFF_LAT   200192     // 64 floats
#define SMEM_TOTAL 200448

// persistent pre-split, pre-swizzled weight images: per layer 32KB hi + 32KB lo
__device__ __align__(16) unsigned char g_wimg[7 * 65536];
__device__ float g_bias[7 * 128];

// ---------------------------------------------------------------------------
__device__ __forceinline__ uint32_t smem_u32(const void* p) {
    uint32_t a;
    asm("{ .reg .u64 t; cvta.to.shared.u64 t, %1; cvt.u32.u64 %0, t; }"
        : "=r"(a) : "l"(p));
    return a;
}

#define LDSM_X4(r0, r1, r2, r3, a) \
    asm volatile("ldmatrix.sync.aligned.m8n8.x4.shared.b16 {%0,%1,%2,%3}, [%4];" \
                 : "=r"(r0), "=r"(r1), "=r"(r2), "=r"(r3) : "r"(a))
#define LDSM_X2(r0, r1, a) \
    asm volatile("ldmatrix.sync.aligned.m8n8.x2.shared.b16 {%0,%1}, [%2];" \
                 : "=r"(r0), "=r"(r1) : "r"(a))

#define MMA_BF16(c, a, b) \
    asm volatile("mma.sync.aligned.m16n8k16.row.col.f32.bf16.bf16.f32 " \
                 "{%0,%1,%2,%3},{%4,%5,%6,%7},{%8,%9},{%0,%1,%2,%3};" \
                 : "+f"((c)[0]), "+f"((c)[1]), "+f"((c)[2]), "+f"((c)[3]) \
                 : "r"((a)[0]), "r"((a)[1]), "r"((a)[2]), "r"((a)[3]), \
                   "r"((b)[0]), "r"((b)[1]))

#define CP_ASYNC16(dst, src) \
    asm volatile("cp.async.cg.shared.global [%0], [%1], 16;" \
                 :: "r"(dst), "l"(src) : "memory")
#define CP_COMMIT() asm volatile("cp.async.commit_group;" ::: "memory")
#define CP_WAIT0()  asm volatile("cp.async.wait_group 0;" ::: "memory")

#define STS32(a, v) \
    asm volatile("st.shared.b32 [%0], %1;" :: "r"(a), "r"(v) : "memory")

__device__ __forceinline__ uint32_t pack_bf2(__nv_bfloat16 a, __nv_bfloat16 b) {
    return (uint32_t)__bfloat16_as_ushort(a) |
           ((uint32_t)__bfloat16_as_ushort(b) << 16);
}

__device__ __forceinline__ void split_pack(float a0, float a1,
                                           uint32_t& hi, uint32_t& lo) {
    __nv_bfloat16 h0 = __float2bfloat16(a0);
    __nv_bfloat16 h1 = __float2bfloat16(a1);
    __nv_bfloat16 l0 = __float2bfloat16(a0 - __bfloat162float(h0));
    __nv_bfloat16 l1 = __float2bfloat16(a1 - __bfloat162float(h1));
    hi = pack_bf2(h0, h1);
    lo = pack_bf2(l0, l1);
}

__device__ __forceinline__ float gelu_exact(float x) {
    return x * normcdff(x);
}

// ---------------------------------------------------------------------------
// prep: split weights to bf16 hi/lo, pre-swizzled W^T tile images.
// Per layer: [hi: chunk(k>>6) x (128 n-rows x 128B)][lo: +32768]
// byte off within chunk: n*128 + (((k&63)*2) ^ ((n&7)<<4)).
// W1 padded K 89->128 with zeros, W7 padded N 9->128 with zeros.
// ---------------------------------------------------------------------------
__global__ void prep_weights(const float* __restrict__ w1, const float* __restrict__ w2,
                             const float* __restrict__ w3, const float* __restrict__ w4,
                             const float* __restrict__ w5, const float* __restrict__ w6,
                             const float* __restrict__ w7) {
    int idx = blockIdx.x * blockDim.x + threadIdx.x;
    if (idx >= 7 * 16384) return;
    int l = idx >> 14;
    int rem = idx & 16383;
    int n = rem >> 7;   // output neuron (tile row)
    int k = rem & 127;  // input index   (tile col)
    int K = (l == 0) ? 89 : 128;
    int N = (l == 6) ? 9 : 128;
    const float* w;
    switch (l) {
        case 0: w = w1; break; case 1: w = w2; break; case 2: w = w3; break;
        case 3: w = w4; break; case 4: w = w5; break; case 5: w = w6; break;
        default: w = w7; break;
    }
    float v = 0.f;
    if (k < K && n < N) v = w[k * N + n];
    __nv_bfloat16 hi = __float2bfloat16(v);
    __nv_bfloat16 lo = __float2bfloat16(v - __bfloat162float(hi));
    size_t off = (size_t)l * 65536 + (size_t)(k >> 6) * 16384 +
                 (uint32_t)(n * 128 + (((k & 63) * 2) ^ ((n & 7) << 4)));
    *(__nv_bfloat16*)(g_wimg + off)         = hi;
    *(__nv_bfloat16*)(g_wimg + off + 32768) = lo;
}

__global__ void prep_bias(const float* __restrict__ b1, const float* __restrict__ b2,
                          const float* __restrict__ b3, const float* __restrict__ b4,
                          const float* __restrict__ b5, const float* __restrict__ b6,
                          const float* __restrict__ b7) {
    int l = blockIdx.x;
    int n = threadIdx.x;
    const float* b;
    switch (l) {
        case 0: b = b1; break; case 1: b = b2; break; case 2: b = b3; break;
        case 3: b = b4; break; case 4: b = b5; break; case 5: b = b6; break;
        default: b = b7; break;
    }
    int N = (l == 6) ? 9 : 128;
    g_bias[l * 128 + n] = (n < N) ? b[n] : 0.f;
}

// ---------------------------------------------------------------------------
// main fused kernel: one CTA = 256 particles; 16 warps in 4x4 tile grid
// warp tile: m64 x n32 (4 mtiles x 4 ntiles of m16n8)
// ---------------------------------------------------------------------------
__global__ void __launch_bounds__(THREADS, 1)
stress_main(const float* __restrict__ F, const float* __restrict__ C,
            const int* __restrict__ traj_id, const float* __restrict__ latent,
            float* __restrict__ out, int Bn) {
    extern __shared__ char smem[];
    const uint32_t sb = smem_u32(smem);
    const int t    = threadIdx.x;
    const int wid  = t >> 5;
    const int lane = t & 31;
    const int mband = wid >> 2;       // 0..3 (x64 rows)
    const int nband = wid & 3;        // 0..3 (x32 cols)
    const int g     = lane >> 2;      // 0..7
    const int tid4  = lane & 3;       // 0..3

    // ---- kick off W[0] prefetch immediately ----
    {
        const char* wsrc = (const char*)g_wimg;
        uint32_t wdst = sb + OFF_WHI;
        #pragma unroll
        for (int i = 0; i < 8; ++i)
            CP_ASYNC16(wdst + (uint32_t)(t + i * 512) * 16, wsrc + (size_t)(t + i * 512) * 16);
        CP_COMMIT();
    }

    // ---- bias + latent to smem ----
    float* bias_sh = (float*)(smem + OFF_BIAS);
    for (int i = t; i < 896; i += THREADS) bias_sh[i] = g_bias[i];
    if (t < 64) {
        int traj = traj_id[0];
        ((float*)(smem + OFF_LAT))[t] = latent[(size_t)traj * 64 + t];
    }

    // ---- stage F, C (coalesced) into X_lo scratch ----
    {
        const float4* Fv = (const float4*)(F + (size_t)blockIdx.x * TILE_M * 9);
        const float4* Cv = (const float4*)(C + (size_t)blockIdx.x * TILE_M * 9);
        float4* s1 = (float4*)(smem + OFF_XLO);
        float4* s2 = (float4*)(smem + OFF_XLO + 9216);
        for (int i = t; i < 576; i += THREADS) { s1[i] = Fv[i]; s2[i] = Cv[i]; }
    }
    __syncthreads();

    float f[9], c9[9];
    if (t < 256) {
        const float* s1 = (const float*)(smem + OFF_XLO);
        const float* s2 = (const float*)(smem + OFF_XLO + 9216);
        #pragma unroll
        for (int i = 0; i < 9; ++i) { f[i] = s1[t * 9 + i]; c9[i] = s2[t * 9 + i]; }
    }
    __syncthreads();

    // ---- feature stage: thread t (<256) owns row t ----
    if (t < 256) {
        const float* lat_sh = (const float*)(smem + OFF_LAT);
        float fe[16];
        #pragma unroll
        for (int i = 0; i < 3; ++i)
            #pragma unroll
            for (int k = 0; k < 3; ++k)
                fe[i * 3 + k] = f[i*3+0]*f[k*3+0] + f[i*3+1]*f[k*3+1] + f[i*3+2]*f[k*3+2];
        float det = f[0]*(f[4]*f[8]-f[5]*f[7]) - f[1]*(f[3]*f[8]-f[5]*f[6])
                  + f[2]*(f[3]*f[7]-f[4]*f[6]);
        float J  = fmaxf(det, 1e-6f);
        float J1 = fmaxf(f[0], 1e-6f);
        // eigenvalues of FFt (trigonometric), singular values = sqrt (descending)
        float a00 = fe[0], a01 = fe[1], a02 = fe[2], a11 = fe[4], a12 = fe[5], a22 = fe[8];
        float q  = (a00 + a11 + a22) * (1.f / 3.f);
        float p1 = a01*a01 + a02*a02 + a12*a12;
        float d0 = a00 - q, d1 = a11 - q, d2 = a22 - q;
        float p2 = d0*d0 + d1*d1 + d2*d2 + 2.f*p1;
        float pp = sqrtf(fmaxf(p2 * (1.f / 6.f), 0.f));
        float ip = 1.f / fmaxf(pp, 1e-20f);
        float b00 = d0*ip, b01 = a01*ip, b02 = a02*ip;
        float b11 = d1*ip, b12 = a12*ip, b22 = d2*ip;
        float detB = b00*(b11*b22 - b12*b12) - b01*(b01*b22 - b12*b02)
                   + b02*(b01*b12 - b11*b02);
        float r = fminf(fmaxf(0.5f * detB, -1.f), 1.f);
        float phi = acosf(r) * (1.f / 3.f);
        float e1 = q + 2.f * pp * cosf(phi);
        float e3 = q + 2.f * pp * cosf(phi + 2.0943951023931953f);
        float e2 = 3.f * q - e1 - e3;
        fe[9]  = logf(J);
        fe[10] = sqrtf(fmaxf(e1, 0.f));
        fe[11] = sqrtf(fmaxf(e2, 0.f));
        fe[12] = sqrtf(fmaxf(e3, 0.f));
        fe[13] = J;
        fe[14] = logf(J1);
        fe[15] = J1;

        uint32_t rowbase = sb + OFF_XHI + (uint32_t)t * 128;
        uint32_t rsw = (uint32_t)(t & 7) << 4;
        #pragma unroll
        for (int n = 0; n < 128; n += 2) {
            #define CVAL(nn) ((nn) < 16 ? fe[(nn)] : ((nn) < 25 ? c9[(nn)-16] : \
                              ((nn) < 89 ? lat_sh[(nn)-25] : 0.f)))
            float v0 = CVAL(n);
            float v1 = CVAL(n + 1);
            #undef CVAL
            uint32_t hi, lo;
            split_pack(v0, v1, hi, lo);
            uint32_t a = rowbase + (uint32_t)((n >> 6) * 32768)
                       + (((uint32_t)(n & 63) << 1) ^ rsw);
            STS32(a, hi);
            STS32(a + 65536, lo);
        }
    }
    CP_WAIT0();
    __syncthreads();   // X[0] + W[0] ready

    // ---- per-lane constant address pieces ----
    const int   ra     = mband * 64 + (lane & 15);
    const uint32_t abase = sb + OFF_XHI + (uint32_t)ra * 128;
    const uint32_t rsw   = (uint32_t)(ra & 7) << 4;
    const uint32_t wbase = sb + OFF_WHI + (uint32_t)(nband * 32 + (lane & 7)) * 128;
    const uint32_t nsw   = (uint32_t)(lane & 7) << 4;
    const uint32_t kA    = (lane & 16) ? 8u : 0u;   // A k sub-offset
    const uint32_t kB    = (uint32_t)(lane & 8);    // B k sub-offset
    // epilogue constants
    const uint32_t echunk = (uint32_t)(nband >> 1) * 32768;
    const uint32_t egsw   = (uint32_t)g << 4;

    for (int l = 0; l < 7; ++l) {
        float acc[4][4][4];
        #pragma unroll
        for (int i = 0; i < 4; ++i)
            #pragma unroll
            for (int j = 0; j < 4; ++j)
                #pragma unroll
                for (int u = 0; u < 4; ++u) acc[i][j][u] = 0.f;

        const int kmax = (l == 0) ? 6 : 8;
        const int ntn  = (l == 6) ? ((nband == 0) ? 2 : 0) : 4;

        if (ntn > 0) {
            for (int ks = 0; ks < kmax; ++ks) {
                uint32_t kkA = (uint32_t)ks * 16 + kA;
                uint32_t kkB = (uint32_t)ks * 16 + kB;
                uint32_t achunk = (uint32_t)(ks >> 2) * 32768;
                uint32_t wchunk = (uint32_t)(ks >> 2) * 16384;
                uint32_t koffA = ((kkA & 63) << 1) ^ rsw;
                uint32_t koffB = ((kkB & 63) << 1) ^ nsw;

                uint32_t bh[4][2], bl[4][2];
                #pragma unroll
                for (int nt = 0; nt < 4; ++nt) {
                    if (nt >= ntn) break;
                    uint32_t ba = wbase + (uint32_t)nt * 1024 + wchunk + koffB;
                    LDSM_X2(bh[nt][0], bh[nt][1], ba);
                    LDSM_X2(bl[nt][0], bl[nt][1], ba + 32768);
                }
                #pragma unroll
                for (int mt = 0; mt < 4; ++mt) {
                    uint32_t aa = abase + (uint32_t)mt * 2048 + achunk + koffA;
                    uint32_t ah[4], al[4];
                    LDSM_X4(ah[0], ah[1], ah[2], ah[3], aa);
                    LDSM_X4(al[0], al[1], al[2], al[3], aa + 65536);
                    #pragma unroll
                    for (int nt = 0; nt < 4; ++nt) {
                        if (nt >= ntn) break;
                        MMA_BF16(acc[mt][nt], ah, bh[nt]);
                        MMA_BF16(acc[mt][nt], ah, bl[nt]);
                        MMA_BF16(acc[mt][nt], al, bh[nt]);
                    }
                }
            }
        }
        __syncthreads();   // all X/W reads complete

        if (l < 6) {
            // prefetch next-layer weights (overlaps epilogue)
            const char* wsrc = (const char*)(g_wimg + (size_t)(l + 1) * 65536);
            uint32_t wdst = sb + OFF_WHI;
            #pragma unroll
            for (int i = 0; i < 8; ++i)
                CP_ASYNC16(wdst + (uint32_t)(t + i * 512) * 16, wsrc + (size_t)(t + i * 512) * 16);
            CP_COMMIT();

            // epilogue: bias + exact GELU + split + store back to X
            const float* bias = bias_sh + l * 128;
            #pragma unroll
            for (int mt = 0; mt < 4; ++mt) {
                uint32_t rb0 = sb + OFF_XHI + (uint32_t)(mband * 64 + mt * 16 + g) * 128;
                uint32_t rb1 = rb0 + 1024;
                #pragma unroll
                for (int nt = 0; nt < 4; ++nt) {
                    int c = nband * 32 + nt * 8 + tid4 * 2;
                    float bc0 = bias[c], bc1 = bias[c + 1];
                    float x00 = gelu_exact(acc[mt][nt][0] + bc0);
                    float x01 = gelu_exact(acc[mt][nt][1] + bc1);
                    float x10 = gelu_exact(acc[mt][nt][2] + bc0);
                    float x11 = gelu_exact(acc[mt][nt][3] + bc1);
                    uint32_t h0, l0, h1, l1;
                    split_pack(x00, x01, h0, l0);
                    split_pack(x10, x11, h1, l1);
                    uint32_t coff = echunk + ((((uint32_t)(c & 63)) << 1) ^ egsw);
                    STS32(rb0 + coff, h0);
                    STS32(rb0 + coff + 65536, l0);
                    STS32(rb1 + coff, h1);
                    STS32(rb1 + coff + 65536, l1);
                }
            }
            CP_WAIT0();
            __syncthreads();   // X[l+1] + W[l+1] ready
        } else {
            // final layer: stage raw outputs (cols 0..8) into smem
            float* stag = (float*)(smem + OFF_XHI);       // [256][12]
            if (nband == 0) {
                const float* bias = bias_sh + 6 * 128;
                #pragma unroll
                for (int mt = 0; mt < 4; ++mt) {
                    int r0 = mband * 64 + mt * 16 + g;
                    #pragma unroll
                    for (int nt = 0; nt < 2; ++nt) {
                        int c = nt * 8 + tid4 * 2;
                        if (c < 9) {
                            stag[r0 * 12 + c]       = acc[mt][nt][0] + bias[c];
                            stag[(r0 + 8) * 12 + c] = acc[mt][nt][2] + bias[c];
                        }
                        if (c + 1 < 9) {
                            stag[r0 * 12 + c + 1]       = acc[mt][nt][1] + bias[c + 1];
                            stag[(r0 + 8) * 12 + c + 1] = acc[mt][nt][3] + bias[c + 1];
                        }
                    }
                }
            }
            __syncthreads();
            float* stag2 = (float*)(smem + OFF_XHI + 16384);  // [256*9]
            if (t < 256) {
                float o[9];
                #pragma unroll
                for (int j = 0; j < 9; ++j) o[j] = stag[t * 12 + j];
                float s01 = 0.5f * (o[1] + o[3]);
                float s02 = 0.5f * (o[2] + o[6]);
                float s12 = 0.5f * (o[5] + o[7]);
                float* d = stag2 + t * 9;
                d[0] = o[0]; d[1] = s01; d[2] = s02;
                d[3] = s01;  d[4] = o[4]; d[5] = s12;
                d[6] = s02;  d[7] = s12;  d[8] = o[8];
            }
            __syncthreads();
            float4* og = (float4*)(out + (size_t)blockIdx.x * TILE_M * 9);
            const float4* sv = (const float4*)stag2;
            for (int i = t; i < 576; i += THREADS) og[i] = sv[i];
        }
    }
}

// ---------------------------------------------------------------------------
extern "C" void kernel_launch(void* const* d_in, const int* in_sizes, int n_in,
                              void* d_out, int out_size) {
    const float* F      = (const float*)d_in[0];
    const float* C      = (const float*)d_in[1];
    const int*   traj   = (const int*)d_in[2];
    const float* latent = (const float*)d_in[3];
    const float* W1 = (const float*)d_in[4];  const float* b1 = (const float*)d_in[5];
    const float* W2 = (const float*)d_in[6];  const float* b2 = (const float*)d_in[7];
    const float* W3 = (const float*)d_in[8];  const float* b3 = (const float*)d_in[9];
    const float* W4 = (const float*)d_in[10]; const float* b4 = (const float*)d_in[11];
    const float* W5 = (const float*)d_in[12]; const float* b5 = (const float*)d_in[13];
    const float* W6 = (const float*)d_in[14]; const float* b6 = (const float*)d_in[15];
    const float* W7 = (const float*)d_in[16]; const float* b7 = (const float*)d_in[17];

    int B = in_sizes[0] / 9;

    prep_weights<<<(7 * 16384 + 255) / 256, 256>>>(W1, W2, W3, W4, W5, W6, W7);
    prep_bias<<<7, 128>>>(b1, b2, b3, b4, b5, b6, b7);

    static int configured = 0;
    cudaFuncSetAttribute(stress_main,
                         cudaFuncAttributeMaxDynamicSharedMemorySize, SMEM_TOTAL);
    (void)configured;

    int grid = (B + TILE_M - 1) / TILE_M;
    stress_main<<<grid, THREADS, SMEM_TOTAL>>>(F, C, traj, latent, (float*)d_out, B);
}

// round 4
// speedup vs baseline: 1.4193x; 1.4193x over previous
#include <cuda_runtime.h>
#include <cuda_bf16.h>
#include <stdint.h>

// ============================================================================
// StressNN on GB300 (sm_103a, plain sm_103 PTX target -> HMMA path)
//   features (FFt, det, analytic 3x3 SVD sigma) + 7-layer MLP, exact GELU
//   GEMMs: mma.sync m16n8k16 bf16, 3-way split (hi@Whi + hi@Wlo + lo@Whi)
// ============================================================================

#define TILE_M   256
#define THREADS  512

// ---- dynamic shared memory layout (bytes) ----
#define OFF_XHI   0          // [2 chunks][256 rows][128B] swizzled
#define OFF_XLO   65536
#define OFF_WHI   131072     // [2 chunks][128 rows][128B] swizzled
#define OFF_WLO   163840
#define OFF_BIAS  196608     // 7*128 floats
#define OFF_LAT   200192     // 64 floats
#define SMEM_TOTAL 200448

// persistent pre-split, pre-swizzled weight images: per layer 32KB hi + 32KB lo
__device__ __align__(16) unsigned char g_wimg[7 * 65536];
__device__ float g_bias[7 * 128];

// ---------------------------------------------------------------------------
__device__ __forceinline__ uint32_t smem_u32(const void* p) {
    uint32_t a;
    asm("{ .reg .u64 t; cvta.to.shared.u64 t, %1; cvt.u32.u64 %0, t; }"
        : "=r"(a) : "l"(p));
    return a;
}

#define LDSM_X4(r0, r1, r2, r3, a) \
    asm volatile("ldmatrix.sync.aligned.m8n8.x4.shared.b16 {%0,%1,%2,%3}, [%4];" \
                 : "=r"(r0), "=r"(r1), "=r"(r2), "=r"(r3) : "r"(a))

#define MMA_BF16(c, a, b) \
    asm volatile("mma.sync.aligned.m16n8k16.row.col.f32.bf16.bf16.f32 " \
                 "{%0,%1,%2,%3},{%4,%5,%6,%7},{%8,%9},{%0,%1,%2,%3};" \
                 : "+f"((c)[0]), "+f"((c)[1]), "+f"((c)[2]), "+f"((c)[3]) \
                 : "r"((a)[0]), "r"((a)[1]), "r"((a)[2]), "r"((a)[3]), \
                   "r"((b)[0]), "r"((b)[1]))

#define CP_ASYNC16(dst, src) \
    asm volatile("cp.async.cg.shared.global [%0], [%1], 16;" \
                 :: "r"(dst), "l"(src) : "memory")
#define CP_COMMIT() asm volatile("cp.async.commit_group;" ::: "memory")
#define CP_WAIT0()  asm volatile("cp.async.wait_group 0;" ::: "memory")

#define STS32(a, v) \
    asm volatile("st.shared.b32 [%0], %1;" :: "r"(a), "r"(v) : "memory")

__device__ __forceinline__ uint32_t pack_bf2(__nv_bfloat16 a, __nv_bfloat16 b) {
    return (uint32_t)__bfloat16_as_ushort(a) |
           ((uint32_t)__bfloat16_as_ushort(b) << 16);
}

__device__ __forceinline__ void split_pack(float a0, float a1,
                                           uint32_t& hi, uint32_t& lo) {
    __nv_bfloat16 h0 = __float2bfloat16(a0);
    __nv_bfloat16 h1 = __float2bfloat16(a1);
    __nv_bfloat16 l0 = __float2bfloat16(a0 - __bfloat162float(h0));
    __nv_bfloat16 l1 = __float2bfloat16(a1 - __bfloat162float(h1));
    hi = pack_bf2(h0, h1);
    lo = pack_bf2(l0, l1);
}

__device__ __forceinline__ float gelu_exact(float x) {
    // exact GELU via erff (fast poly path, ~2 ulp), not normcdff->erfcf
    return 0.5f * x * (1.0f + erff(x * 0.70710678118654752f));
}

// ---------------------------------------------------------------------------
// prep (single kernel so ncu skip-5 lands on stress_main):
// split weights to bf16 hi/lo, pre-swizzled W^T tile images + bias copy.
// Per layer: [hi: chunk(k>>6) x (128 n-rows x 128B)][lo: +32768]
// byte off within chunk: n*128 + (((k&63)*2) ^ ((n&7)<<4)).
// W1 padded K 89->128 with zeros, W7 padded N 9->128 with zeros.
// ---------------------------------------------------------------------------
__global__ void prep_all(const float* __restrict__ w1, const float* __restrict__ w2,
                         const float* __restrict__ w3, const float* __restrict__ w4,
                         const float* __restrict__ w5, const float* __restrict__ w6,
                         const float* __restrict__ w7,
                         const float* __restrict__ b1, const float* __restrict__ b2,
                         const float* __restrict__ b3, const float* __restrict__ b4,
                         const float* __restrict__ b5, const float* __restrict__ b6,
                         const float* __restrict__ b7) {
    int idx = blockIdx.x * blockDim.x + threadIdx.x;
    if (idx < 7 * 16384) {
        int l = idx >> 14;
        int rem = idx & 16383;
        int n = rem >> 7;   // output neuron (tile row)
        int k = rem & 127;  // input index   (tile col)
        int K = (l == 0) ? 89 : 128;
        int N = (l == 6) ? 9 : 128;
        const float* w;
        switch (l) {
            case 0: w = w1; break; case 1: w = w2; break; case 2: w = w3; break;
            case 3: w = w4; break; case 4: w = w5; break; case 5: w = w6; break;
            default: w = w7; break;
        }
        float v = 0.f;
        if (k < K && n < N) v = w[k * N + n];
        __nv_bfloat16 hi = __float2bfloat16(v);
        __nv_bfloat16 lo = __float2bfloat16(v - __bfloat162float(hi));
        size_t off = (size_t)l * 65536 + (size_t)(k >> 6) * 16384 +
                     (uint32_t)(n * 128 + (((k & 63) * 2) ^ ((n & 7) << 4)));
        *(__nv_bfloat16*)(g_wimg + off)         = hi;
        *(__nv_bfloat16*)(g_wimg + off + 32768) = lo;
    }
    if (idx < 7 * 128) {
        int l = idx >> 7;
        int n = idx & 127;
        const float* b;
        switch (l) {
            case 0: b = b1; break; case 1: b = b2; break; case 2: b = b3; break;
            case 3: b = b4; break; case 4: b = b5; break; case 5: b = b6; break;
            default: b = b7; break;
        }
        int N = (l == 6) ? 9 : 128;
        g_bias[idx] = (n < N) ? b[n] : 0.f;
    }
}

// ---------------------------------------------------------------------------
// main fused kernel: one CTA = 256 particles; 16 warps in 4x4 tile grid
// warp tile: m64 x n32 (4 mtiles x 4 ntiles of m16n8)
// ---------------------------------------------------------------------------
__global__ void __launch_bounds__(THREADS, 1)
stress_main(const float* __restrict__ F, const float* __restrict__ C,
            const int* __restrict__ traj_id, const float* __restrict__ latent,
            float* __restrict__ out, int Bn) {
    extern __shared__ char smem[];
    const uint32_t sb = smem_u32(smem);
    const int t    = threadIdx.x;
    const int wid  = t >> 5;
    const int lane = t & 31;
    const int mband = wid >> 2;       // 0..3 (x64 rows)
    const int nband = wid & 3;        // 0..3 (x32 cols)
    const int g     = lane >> 2;      // 0..7
    const int tid4  = lane & 3;       // 0..3

    // ---- kick off W[0] prefetch immediately ----
    {
        const char* wsrc = (const char*)g_wimg;
        uint32_t wdst = sb + OFF_WHI;
        #pragma unroll
        for (int i = 0; i < 8; ++i)
            CP_ASYNC16(wdst + (uint32_t)(t + i * 512) * 16, wsrc + (size_t)(t + i * 512) * 16);
        CP_COMMIT();
    }

    // ---- bias + latent to smem ----
    float* bias_sh = (float*)(smem + OFF_BIAS);
    for (int i = t; i < 896; i += THREADS) bias_sh[i] = g_bias[i];
    if (t < 64) {
        int traj = traj_id[0];
        ((float*)(smem + OFF_LAT))[t] = latent[(size_t)traj * 64 + t];
    }

    // ---- stage F, C (coalesced) into X_lo scratch ----
    {
        const float4* Fv = (const float4*)(F + (size_t)blockIdx.x * TILE_M * 9);
        const float4* Cv = (const float4*)(C + (size_t)blockIdx.x * TILE_M * 9);
        float4* s1 = (float4*)(smem + OFF_XLO);
        float4* s2 = (float4*)(smem + OFF_XLO + 9216);
        for (int i = t; i < 576; i += THREADS) { s1[i] = Fv[i]; s2[i] = Cv[i]; }
    }
    __syncthreads();

    float f[9], c9[9];
    if (t < 256) {
        const float* s1 = (const float*)(smem + OFF_XLO);
        const float* s2 = (const float*)(smem + OFF_XLO + 9216);
        #pragma unroll
        for (int i = 0; i < 9; ++i) { f[i] = s1[t * 9 + i]; c9[i] = s2[t * 9 + i]; }
    }
    __syncthreads();

    // ---- feature stage: thread t (<256) owns row t ----
    if (t < 256) {
        const float* lat_sh = (const float*)(smem + OFF_LAT);
        float fe[16];
        #pragma unroll
        for (int i = 0; i < 3; ++i)
            #pragma unroll
            for (int k = 0; k < 3; ++k)
                fe[i * 3 + k] = f[i*3+0]*f[k*3+0] + f[i*3+1]*f[k*3+1] + f[i*3+2]*f[k*3+2];
        float det = f[0]*(f[4]*f[8]-f[5]*f[7]) - f[1]*(f[3]*f[8]-f[5]*f[6])
                  + f[2]*(f[3]*f[7]-f[4]*f[6]);
        float J  = fmaxf(det, 1e-6f);
        float J1 = fmaxf(f[0], 1e-6f);
        // eigenvalues of FFt (trigonometric), singular values = sqrt (descending)
        float a00 = fe[0], a01 = fe[1], a02 = fe[2], a11 = fe[4], a12 = fe[5], a22 = fe[8];
        float q  = (a00 + a11 + a22) * (1.f / 3.f);
        float p1 = a01*a01 + a02*a02 + a12*a12;
        float d0 = a00 - q, d1 = a11 - q, d2 = a22 - q;
        float p2 = d0*d0 + d1*d1 + d2*d2 + 2.f*p1;
        float pp = sqrtf(fmaxf(p2 * (1.f / 6.f), 0.f));
        float ip = 1.f / fmaxf(pp, 1e-20f);
        float b00 = d0*ip, b01 = a01*ip, b02 = a02*ip;
        float b11 = d1*ip, b12 = a12*ip, b22 = d2*ip;
        float detB = b00*(b11*b22 - b12*b12) - b01*(b01*b22 - b12*b02)
                   + b02*(b01*b12 - b11*b02);
        float r = fminf(fmaxf(0.5f * detB, -1.f), 1.f);
        float phi = acosf(r) * (1.f / 3.f);
        float e1 = q + 2.f * pp * cosf(phi);
        float e3 = q + 2.f * pp * cosf(phi + 2.0943951023931953f);
        float e2 = 3.f * q - e1 - e3;
        fe[9]  = logf(J);
        fe[10] = sqrtf(fmaxf(e1, 0.f));
        fe[11] = sqrtf(fmaxf(e2, 0.f));
        fe[12] = sqrtf(fmaxf(e3, 0.f));
        fe[13] = J;
        fe[14] = logf(J1);
        fe[15] = J1;

        uint32_t rowbase = sb + OFF_XHI + (uint32_t)t * 128;
        uint32_t rsw = (uint32_t)(t & 7) << 4;
        #pragma unroll
        for (int n = 0; n < 128; n += 2) {
            #define CVAL(nn) ((nn) < 16 ? fe[(nn)] : ((nn) < 25 ? c9[(nn)-16] : \
                              ((nn) < 89 ? lat_sh[(nn)-25] : 0.f)))
            float v0 = CVAL(n);
            float v1 = CVAL(n + 1);
            #undef CVAL
            uint32_t hi, lo;
            split_pack(v0, v1, hi, lo);
            uint32_t a = rowbase + (uint32_t)((n >> 6) * 32768)
                       + (((uint32_t)(n & 63) << 1) ^ rsw);
            STS32(a, hi);
            STS32(a + 65536, lo);
        }
    }
    CP_WAIT0();
    __syncthreads();   // X[0] + W[0] ready

    // ---- per-lane constant address pieces ----
    const int   ra     = mband * 64 + (lane & 15);
    const uint32_t abase = sb + OFF_XHI + (uint32_t)ra * 128;
    const uint32_t rsw   = (uint32_t)(ra & 7) << 4;
    // B via ldmatrix.x4 over ntile pairs: lanes 16-31 address rows +8
    const uint32_t wbase4 = sb + OFF_WHI +
        (uint32_t)(nband * 32 + (lane & 7) + (((uint32_t)lane >> 4) << 3)) * 128;
    const uint32_t nsw   = (uint32_t)(lane & 7) << 4;
    const uint32_t kA    = (lane & 16) ? 8u : 0u;   // A k sub-offset
    const uint32_t kB    = (uint32_t)(lane & 8);    // B k sub-offset
    // epilogue constants
    const uint32_t echunk = (uint32_t)(nband >> 1) * 32768;
    const uint32_t egsw   = (uint32_t)g << 4;

    // ================= layers 0..5 (uniform, fully unrolled) =================
    #pragma unroll 1
    for (int l = 0; l < 6; ++l) {
        float acc[4][4][4];
        #pragma unroll
        for (int i = 0; i < 4; ++i)
            #pragma unroll
            for (int j = 0; j < 4; ++j)
                #pragma unroll
                for (int u = 0; u < 4; ++u) acc[i][j][u] = 0.f;

        #pragma unroll
        for (int ks = 0; ks < 8; ++ks) {
            uint32_t kkA = (uint32_t)ks * 16 + kA;
            uint32_t kkB = (uint32_t)ks * 16 + kB;
            uint32_t achunk = (uint32_t)(ks >> 2) * 32768;
            uint32_t wchunk = (uint32_t)(ks >> 2) * 16384;
            uint32_t koffA = ((kkA & 63) << 1) ^ rsw;
            uint32_t koffB = ((kkB & 63) << 1) ^ nsw;

            uint32_t bh[8], bl[8];
            #pragma unroll
            for (int p = 0; p < 2; ++p) {
                uint32_t ba = wbase4 + (uint32_t)p * 2048 + wchunk + koffB;
                LDSM_X4(bh[p*4+0], bh[p*4+1], bh[p*4+2], bh[p*4+3], ba);
                LDSM_X4(bl[p*4+0], bl[p*4+1], bl[p*4+2], bl[p*4+3], ba + 32768);
            }
            #pragma unroll
            for (int mt = 0; mt < 4; ++mt) {
                uint32_t aa = abase + (uint32_t)mt * 2048 + achunk + koffA;
                uint32_t ah[4], al[4];
                LDSM_X4(ah[0], ah[1], ah[2], ah[3], aa);
                LDSM_X4(al[0], al[1], al[2], al[3], aa + 65536);
                #pragma unroll
                for (int nt = 0; nt < 4; ++nt) {
                    MMA_BF16(acc[mt][nt], ah, bh + nt * 2);
                    MMA_BF16(acc[mt][nt], ah, bl + nt * 2);
                    MMA_BF16(acc[mt][nt], al, bh + nt * 2);
                }
            }
        }
        __syncthreads();   // all X/W reads complete

        // prefetch next-layer weights (overlaps epilogue)
        {
            const char* wsrc = (const char*)(g_wimg + (size_t)(l + 1) * 65536);
            uint32_t wdst = sb + OFF_WHI;
            #pragma unroll
            for (int i = 0; i < 8; ++i)
                CP_ASYNC16(wdst + (uint32_t)(t + i * 512) * 16, wsrc + (size_t)(t + i * 512) * 16);
            CP_COMMIT();
        }

        // epilogue: bias + exact GELU + split + store back to X
        {
            const float* bias = bias_sh + l * 128;
            float bc0[4], bc1[4];
            #pragma unroll
            for (int nt = 0; nt < 4; ++nt) {
                int c = nband * 32 + nt * 8 + tid4 * 2;
                bc0[nt] = bias[c];
                bc1[nt] = bias[c + 1];
            }
            #pragma unroll
            for (int mt = 0; mt < 4; ++mt) {
                uint32_t rb0 = sb + OFF_XHI + (uint32_t)(mband * 64 + mt * 16 + g) * 128;
                uint32_t rb1 = rb0 + 1024;
                #pragma unroll
                for (int nt = 0; nt < 4; ++nt) {
                    int c = nband * 32 + nt * 8 + tid4 * 2;
                    float x00 = gelu_exact(acc[mt][nt][0] + bc0[nt]);
                    float x01 = gelu_exact(acc[mt][nt][1] + bc1[nt]);
                    float x10 = gelu_exact(acc[mt][nt][2] + bc0[nt]);
                    float x11 = gelu_exact(acc[mt][nt][3] + bc1[nt]);
                    uint32_t h0, l0, h1, l1;
                    split_pack(x00, x01, h0, l0);
                    split_pack(x10, x11, h1, l1);
                    uint32_t coff = echunk + ((((uint32_t)(c & 63)) << 1) ^ egsw);
                    STS32(rb0 + coff, h0);
                    STS32(rb0 + coff + 65536, l0);
                    STS32(rb1 + coff, h1);
                    STS32(rb1 + coff + 65536, l1);
                }
            }
        }
        CP_WAIT0();
        __syncthreads();   // X[l+1] + W[l+1] ready
    }

    // ================= layer 6 (N=9, only nband==0 warps) ====================
    {
        float acc[4][2][4];
        #pragma unroll
        for (int i = 0; i < 4; ++i)
            #pragma unroll
            for (int j = 0; j < 2; ++j)
                #pragma unroll
                for (int u = 0; u < 4; ++u) acc[i][j][u] = 0.f;

        if (nband == 0) {
            #pragma unroll
            for (int ks = 0; ks < 8; ++ks) {
                uint32_t kkA = (uint32_t)ks * 16 + kA;
                uint32_t kkB = (uint32_t)ks * 16 + kB;
                uint32_t achunk = (uint32_t)(ks >> 2) * 32768;
                uint32_t wchunk = (uint32_t)(ks >> 2) * 16384;
                uint32_t koffA = ((kkA & 63) << 1) ^ rsw;
                uint32_t koffB = ((kkB & 63) << 1) ^ nsw;

                uint32_t bh[4], bl[4];
                uint32_t ba = wbase4 + wchunk + koffB;
                LDSM_X4(bh[0], bh[1], bh[2], bh[3], ba);
                LDSM_X4(bl[0], bl[1], bl[2], bl[3], ba + 32768);
                #pragma unroll
                for (int mt = 0; mt < 4; ++mt) {
                    uint32_t aa = abase + (uint32_t)mt * 2048 + achunk + koffA;
                    uint32_t ah[4], al[4];
                    LDSM_X4(ah[0], ah[1], ah[2], ah[3], aa);
                    LDSM_X4(al[0], al[1], al[2], al[3], aa + 65536);
                    #pragma unroll
                    for (int nt = 0; nt < 2; ++nt) {
                        MMA_BF16(acc[mt][nt], ah, bh + nt * 2);
                        MMA_BF16(acc[mt][nt], ah, bl + nt * 2);
                        MMA_BF16(acc[mt][nt], al, bh + nt * 2);
                    }
                }
            }
        }
        __syncthreads();

        // stage raw outputs (cols 0..8) into smem
        float* stag = (float*)(smem + OFF_XHI);       // [256][12]
        if (nband == 0) {
            const float* bias = bias_sh + 6 * 128;
            #pragma unroll
            for (int mt = 0; mt < 4; ++mt) {
                int r0 = mband * 64 + mt * 16 + g;
                #pragma unroll
                for (int nt = 0; nt < 2; ++nt) {
                    int c = nt * 8 + tid4 * 2;
                    if (c < 9) {
                        stag[r0 * 12 + c]       = acc[mt][nt][0] + bias[c];
                        stag[(r0 + 8) * 12 + c] = acc[mt][nt][2] + bias[c];
                    }
                    if (c + 1 < 9) {
                        stag[r0 * 12 + c + 1]       = acc[mt][nt][1] + bias[c + 1];
                        stag[(r0 + 8) * 12 + c + 1] = acc[mt][nt][3] + bias[c + 1];
                    }
                }
            }
        }
        __syncthreads();
        float* stag2 = (float*)(smem + OFF_XHI + 16384);  // [256*9]
        if (t < 256) {
            float o[9];
            #pragma unroll
            for (int j = 0; j < 9; ++j) o[j] = stag[t * 12 + j];
            float s01 = 0.5f * (o[1] + o[3]);
            float s02 = 0.5f * (o[2] + o[6]);
            float s12 = 0.5f * (o[5] + o[7]);
            float* d = stag2 + t * 9;
            d[0] = o[0]; d[1] = s01; d[2] = s02;
            d[3] = s01;  d[4] = o[4]; d[5] = s12;
            d[6] = s02;  d[7] = s12;  d[8] = o[8];
        }
        __syncthreads();
        float4* og = (float4*)(out + (size_t)blockIdx.x * TILE_M * 9);
        const float4* sv = (const float4*)stag2;
        for (int i = t; i < 576; i += THREADS) og[i] = sv[i];
    }
}

// ---------------------------------------------------------------------------
extern "C" void kernel_launch(void* const* d_in, const int* in_sizes, int n_in,
                              void* d_out, int out_size) {
    const float* F      = (const float*)d_in[0];
    const float* C      = (const float*)d_in[1];
    const int*   traj   = (const int*)d_in[2];
    const float* latent = (const float*)d_in[3];
    const float* W1 = (const float*)d_in[4];  const float* b1 = (const float*)d_in[5];
    const float* W2 = (const float*)d_in[6];  const float* b2 = (const float*)d_in[7];
    const float* W3 = (const float*)d_in[8];  const float* b3 = (const float*)d_in[9];
    const float* W4 = (const float*)d_in[10]; const float* b4 = (const float*)d_in[11];
    const float* W5 = (const float*)d_in[12]; const float* b5 = (const float*)d_in[13];
    const float* W6 = (const float*)d_in[14]; const float* b6 = (const float*)d_in[15];
    const float* W7 = (const float*)d_in[16]; const float* b7 = (const float*)d_in[17];

    int B = in_sizes[0] / 9;

    prep_all<<<(7 * 16384 + 255) / 256, 256>>>(W1, W2, W3, W4, W5, W6, W7,
                                               b1, b2, b3, b4, b5, b6, b7);

    cudaFuncSetAttribute(stress_main,
                         cudaFuncAttributeMaxDynamicSharedMemorySize, SMEM_TOTAL);

    int grid = (B + TILE_M - 1) / TILE_M;
    stress_main<<<grid, THREADS, SMEM_TOTAL>>>(F, C, traj, latent, (float*)d_out, B);
}